// round 3
// baseline (speedup 1.0000x reference)
#include <cuda_runtime.h>
#include <math.h>

#define NPIX   (8*256*256)      // 524288 pixels
#define NCH    32
#define NCLASS 8
#define PAIRS  272              // packed (even-length) lower-tri pairs per class
#define FLT2S  544              // = PAIRS*2 float2 entries per class
#define TPB    128
#define PPT    4
#define PPB    (TPB*PPT)        // 512 pixels per block
#define NBLK   (NPIX/PPB)       // 1024 blocks

typedef unsigned long long ull;

// All per-class constants, staged device->constant each launch.
struct __align__(16) CBlob {
    float4 L[NCLASS * PAIRS];   // Linv rows padded even, pairs splatted (v0,v0,v1,v1)
    float2 nw[NCLASS * NCH];    // -(Linv_k @ mean_k), splatted
    float  logc[NCLASS];        // -16*log(2pi) - logdet_k
};
__device__   CBlob d_blob;      // written by setup kernel
__constant__ CBlob c_blob;      // read by main kernel via constant port (LDCU)

// ---------- packed f32x2 helpers (sm_103a FFMA2/FADD2 — PTX only) ----------
__device__ __forceinline__ ull ffma2(ull a, ull b, ull c) {
    ull d;
    asm("fma.rn.f32x2 %0, %1, %2, %3;" : "=l"(d) : "l"(a), "l"(b), "l"(c));
    return d;
}
__device__ __forceinline__ ull add2(ull a, ull b) {
    ull d;
    asm("add.rn.f32x2 %0, %1, %2;" : "=l"(d) : "l"(a), "l"(b));
    return d;
}
__device__ __forceinline__ ull pack2(float lo, float hi) {
    ull d;
    asm("mov.b64 %0, {%1, %2};" : "=l"(d) : "f"(lo), "f"(hi));
    return d;
}
__device__ __forceinline__ float2 unpack2(ull v) {
    float lo, hi;
    asm("mov.b64 {%0, %1}, %2;" : "=f"(lo), "=f"(hi) : "l"(v));
    return make_float2(lo, hi);
}

// ---------------- setup: triangular inverse, whitened means, log-consts ----------------
// One warp per class; lane j computes column j of Linv by forward substitution.
__global__ void setup_kernel(const float* __restrict__ mean,
                             const float* __restrict__ scale) {
    __shared__ float sInv[NCLASS][NCH][NCH + 1];
    const int k = threadIdx.x >> 5;   // class (8 warps, 256 threads)
    const int j = threadIdx.x & 31;   // column
    const float* Lg = scale + k * NCH * NCH;

    float xcol[NCH];
    #pragma unroll
    for (int i = 0; i < NCH; i++) {
        float s = (i == j) ? 1.0f : 0.0f;
        #pragma unroll
        for (int d = 0; d < i; d++)
            s -= Lg[i * NCH + d] * xcol[d];   // lower triangle only (tril implied)
        xcol[i] = s / Lg[i * NCH + i];
    }

    #pragma unroll
    for (int i = 0; i < NCH; i++) sInv[k][i][j] = xcol[i];

    // packed splatted Linv rows, padded to even length. Row c occupies
    // (c+2)&~1 float2 slots; entry d written by lane d, pad slot zeroed.
    float2* Lp = reinterpret_cast<float2*>(d_blob.L);
    int off2 = 0;
    #pragma unroll
    for (int c = 0; c < NCH; c++) {
        if (j <= c)
            Lp[k * FLT2S + off2 + j] = make_float2(xcol[c], xcol[c]);
        if (((c & 1) == 0) && (j == c + 1))
            Lp[k * FLT2S + off2 + j] = make_float2(0.0f, 0.0f);
        off2 += (c + 2) & ~1;
    }
    __syncwarp();

    // w_j = sum_{d<=j} Linv[j][d] * mean[k][d]  (store negated, splatted)
    float w = 0.0f;
    for (int d = 0; d <= j; d++)
        w += sInv[k][j][d] * mean[k * NCH + d];
    d_blob.nw[k * NCH + j] = make_float2(-w, -w);

    if (j == 0) {
        float ld = 0.0f;
        for (int c = 0; c < NCH; c++)
            ld += logf(fabsf(Lg[c * NCH + c]));
        d_blob.logc[k] = -16.0f * 1.8378770664093453f - ld;   // -0.5*32*log(2pi)-logdet
    }
}

// ---------------- main fused kernel ----------------
__global__ void __launch_bounds__(TPB, 3)
main_kernel(const float* __restrict__ x, float* __restrict__ out) {
    __shared__ float sG[PPB * 9];          // 18432 B (stride 9: conflict-light)

    const int tid = threadIdx.x;
    const int pix0 = blockIdx.x * PPB + tid * PPT;

    // ---- load 4 pixels of x, packed into f32x2 pairs (px0,px1)->xA, (px2,px3)->xB
    ull xA[NCH], xB[NCH];
    {
        const float4* x4 = reinterpret_cast<const float4*>(x);
        const size_t b0 = (size_t)(pix0 + 0) * 8;
        const size_t b1 = (size_t)(pix0 + 1) * 8;
        const size_t b2 = (size_t)(pix0 + 2) * 8;
        const size_t b3 = (size_t)(pix0 + 3) * 8;
        #pragma unroll
        for (int t = 0; t < 8; t++) {
            float4 a = x4[b0 + t], b = x4[b1 + t];
            xA[4*t+0] = pack2(a.x, b.x); xA[4*t+1] = pack2(a.y, b.y);
            xA[4*t+2] = pack2(a.z, b.z); xA[4*t+3] = pack2(a.w, b.w);
        }
        #pragma unroll
        for (int t = 0; t < 8; t++) {
            float4 a = x4[b2 + t], b = x4[b3 + t];
            xB[4*t+0] = pack2(a.x, b.x); xB[4*t+1] = pack2(a.y, b.y);
            xB[4*t+2] = pack2(a.z, b.z); xB[4*t+3] = pack2(a.w, b.w);
        }
    }

    // ---- per-class triangular whitening: z = Linv x - w ; maha = sum z^2
    // Warp-uniform L comes over the CONSTANT port (LDCU) — zero L1tex traffic.
    // One 16B const load (splatted pair) feeds 4 FFMA2; even/odd partials give
    // 4 independent chains per pixel-pair.
    #pragma unroll 1
    for (int k = 0; k < NCLASS; k++) {
        const float4* Lk = c_blob.L + k * PAIRS;
        const ull* nwk = reinterpret_cast<const ull*>(c_blob.nw + k * NCH);
        ull mA = 0ULL, mB = 0ULL;   // (+0.0f, +0.0f)
        int off = 0;
        #pragma unroll
        for (int c = 0; c < NCH; c++) {
            const int np = (c + 2) >> 1;      // pairs in this (padded) row
            ull zA  = nwk[c], zB = zA;        // even-d partial, init with -w
            ull zA2 = 0ULL,  zB2 = 0ULL;      // odd-d partial
            #pragma unroll
            for (int p = 0; p < np; p++) {
                ulonglong2 lw =
                    *reinterpret_cast<const ulonglong2*>(Lk + off + p);
                zA  = ffma2(xA[2*p    ], lw.x, zA);
                zB  = ffma2(xB[2*p    ], lw.x, zB);
                zA2 = ffma2(xA[2*p + 1], lw.y, zA2);
                zB2 = ffma2(xB[2*p + 1], lw.y, zB2);
            }
            ull zAt = add2(zA, zA2);
            ull zBt = add2(zB, zB2);
            mA = ffma2(zAt, zAt, mA);
            mB = ffma2(zBt, zBt, mB);
            off += np;
        }
        float2 a = unpack2(mA), b = unpack2(mB);
        float lc = c_blob.logc[k];
        int base = (tid * PPT) * 9 + k;
        sG[base     ] = fmaf(-0.5f, a.x, lc);
        sG[base +  9] = fmaf(-0.5f, a.y, lc);
        sG[base + 18] = fmaf(-0.5f, b.x, lc);
        sG[base + 27] = fmaf(-0.5f, b.y, lc);
    }

    // ---- epilogue: log-probs -> l2-normalized (with 1e-12 clamp) gauss weights
    #pragma unroll
    for (int q = 0; q < PPT; q++) {
        const int p = tid * PPT + q;
        float lp[NCLASS];
        #pragma unroll
        for (int k = 0; k < NCLASS; k++) lp[k] = sG[p * 9 + k];
        float m = lp[0];
        #pragma unroll
        for (int k = 1; k < NCLASS; k++) m = fmaxf(m, lp[k]);
        float pr[NCLASS];
        float s = 0.0f;
        #pragma unroll
        for (int k = 0; k < NCLASS; k++) {
            pr[k] = __expf(lp[k] - m);
            s = fmaf(pr[k], pr[k], s);     // s >= 1 always (max term is 1)
        }
        float em = __expf(m);
        float t = em * em * s;             // true sum(prob^2); underflow -> clamp path
        float sc = (t >= 1e-12f) ? rsqrtf(s) : (em * 1.0e6f);
        #pragma unroll
        for (int k = 0; k < NCLASS; k++) sG[p * 9 + k] = pr[k] * sc;
    }
    __syncthreads();

    // ---- store phase: one warp per pixel, fully coalesced 512B STG.128 bursts
    const int lane = tid & 31;
    const int wrp  = tid >> 5;
    const float4* x4 = reinterpret_cast<const float4*>(x);
    float4* o4 = reinterpret_cast<float4*>(out);
    for (int p = wrp; p < PPB; p += TPB / 32) {
        const size_t gp = (size_t)blockIdx.x * PPB + p;
        float4 xv = __ldg(&x4[gp * 8 + (lane & 7)]);        // one 128B line, L1/L2-hot
        float g0 = sG[p * 9 + (lane >> 3)];                 // classes 0..3
        float g1 = sG[p * 9 + 4 + (lane >> 3)];             // classes 4..7
        float4 r0, r1;
        r0.x = xv.x * g0; r0.y = xv.y * g0; r0.z = xv.z * g0; r0.w = xv.w * g0;
        r1.x = xv.x * g1; r1.y = xv.y * g1; r1.z = xv.z * g1; r1.w = xv.w * g1;
        __stcs(&o4[gp * 64 + lane],      r0);               // streaming: don't thrash L2
        __stcs(&o4[gp * 64 + 32 + lane], r1);
    }
}

extern "C" void kernel_launch(void* const* d_in, const int* in_sizes, int n_in,
                              void* d_out, int out_size) {
    const float* x     = (const float*)d_in[0];   // [8,256,256,32]
    const float* mean  = (const float*)d_in[1];   // [8,32]
    const float* scale = (const float*)d_in[2];   // [8,32,32]
    float* out = (float*)d_out;                   // [8,256,256,256]

    setup_kernel<<<1, 256>>>(mean, scale);

    // Stage device blob into the constant bank (D2D async: graph-capturable).
    void* blobAddr = nullptr;
    cudaGetSymbolAddress(&blobAddr, d_blob);
    cudaMemcpyToSymbolAsync(c_blob, blobAddr, sizeof(CBlob), 0,
                            cudaMemcpyDeviceToDevice, 0);

    main_kernel<<<NBLK, TPB>>>(x, out);
}

// round 4
// speedup vs baseline: 1.7912x; 1.7912x over previous
#include <cuda_runtime.h>
#include <math.h>

#define NPIX   (8*256*256)      // 524288 pixels
#define NCH    32
#define NCLASS 8
#define PAIRS  272              // channel-pairs per class (rows padded to even)
#define LFLTS  (PAIRS*2)        // 544 floats per class
#define TPB    128
#define PPT    4
#define PPB    (TPB*PPT)        // 512 pixels per block
#define NBLK   (NPIX/PPB)       // 1024 blocks

typedef unsigned long long ull;

// Precomputed per-class constants (written by setup kernel each launch)
__device__ float  d_Lpair[NCLASS*LFLTS]; // Linv rows, raw channel pairs, even-padded
__device__ float2 d_nw[NCLASS*NCH];      // (-(Linv_k@mean_k)[c], 0)  -> packed z init
__device__ float  d_logc[NCLASS];        // -16*log(2pi) - logdet_k

// ---------- packed f32x2 helpers (sm_103a FFMA2 — PTX only) ----------
__device__ __forceinline__ ull ffma2(ull a, ull b, ull c) {
    ull d;
    asm("fma.rn.f32x2 %0, %1, %2, %3;" : "=l"(d) : "l"(a), "l"(b), "l"(c));
    return d;
}
__device__ __forceinline__ float2 unpack2(ull v) {
    float lo, hi;
    asm("mov.b64 {%0, %1}, %2;" : "=f"(lo), "=f"(hi) : "l"(v));
    return make_float2(lo, hi);
}

// ---------------- setup: triangular inverse, whitened means, log-consts ----------------
// One warp per class; lane j computes column j of Linv by forward substitution.
__global__ void setup_kernel(const float* __restrict__ mean,
                             const float* __restrict__ scale) {
    __shared__ float sInv[NCLASS][NCH][NCH + 1];
    const int k = threadIdx.x >> 5;   // class (8 warps, 256 threads)
    const int j = threadIdx.x & 31;   // column
    const float* Lg = scale + k * NCH * NCH;

    float xcol[NCH];
    #pragma unroll
    for (int i = 0; i < NCH; i++) {
        float s = (i == j) ? 1.0f : 0.0f;
        #pragma unroll
        for (int d = 0; d < i; d++)
            s -= Lg[i * NCH + d] * xcol[d];   // lower triangle only (tril implied)
        xcol[i] = s / Lg[i * NCH + i];
    }

    #pragma unroll
    for (int i = 0; i < NCH; i++) sInv[k][i][j] = xcol[i];

    // raw channel-pair rows: row c holds L[c,0..c] at float offsets base+d,
    // pad base+c+1 with 0 when c is even. base advances by (c+2)&~1.
    int base = 0;
    #pragma unroll
    for (int c = 0; c < NCH; c++) {
        if (j <= c)
            d_Lpair[k * LFLTS + base + j] = xcol[c];      // L[c, d=j] = Linv[c][j]
        if (((c & 1) == 0) && (j == c + 1))
            d_Lpair[k * LFLTS + base + j] = 0.0f;
        base += (c + 2) & ~1;
    }
    __syncwarp();

    // w_j = sum_{d<=j} Linv[j][d] * mean[k][d]; packed z-init = (-w, 0)
    float w = 0.0f;
    for (int d = 0; d <= j; d++)
        w += sInv[k][j][d] * mean[k * NCH + d];
    d_nw[k * NCH + j] = make_float2(-w, 0.0f);

    if (j == 0) {
        float ld = 0.0f;
        for (int c = 0; c < NCH; c++)
            ld += logf(fabsf(Lg[c * NCH + c]));
        d_logc[k] = -16.0f * 1.8378770664093453f - ld;   // -0.5*32*log(2pi)-logdet
    }
}

// ---------------- main fused kernel ----------------
__global__ void __launch_bounds__(TPB, 3)
main_kernel(const float* __restrict__ x, float* __restrict__ out) {
    __shared__ float  sL[NCLASS * LFLTS];   // 17408 B raw pairs
    __shared__ float2 sNW[NCLASS * NCH];    //  2048 B
    __shared__ float  sLogc[NCLASS];        //    32 B
    __shared__ float  sG[PPB * 9];          // 18432 B (stride 9: conflict-light)

    const int tid = threadIdx.x;
    const int pix0 = blockIdx.x * PPB + tid * PPT;

    // ---- load 4 pixels of x as channel-pairs: xp[p][j] = (x[2j], x[2j+1]).
    // This is the natural layout — raw 16B loads, zero pack instructions.
    ull xp[PPT][NCH/2];
    {
        const ulonglong2* xg = reinterpret_cast<const ulonglong2*>(x);
        #pragma unroll
        for (int p = 0; p < PPT; p++) {
            const size_t b = (size_t)(pix0 + p) * 8;   // 8 ulonglong2 per pixel
            #pragma unroll
            for (int t = 0; t < 8; t++) {
                ulonglong2 v = xg[b + t];
                xp[p][2*t]   = v.x;
                xp[p][2*t+1] = v.y;
            }
        }
    }

    // ---- fill shared constants
    {
        const float4* Ls = reinterpret_cast<const float4*>(d_Lpair);
        float4* Ld = reinterpret_cast<float4*>(sL);
        for (int i = tid; i < NCLASS * LFLTS / 4; i += TPB) Ld[i] = Ls[i];
        for (int i = tid; i < NCLASS * NCH; i += TPB) sNW[i] = d_nw[i];
        if (tid < NCLASS) sLogc[tid] = d_logc[tid];
    }
    __syncthreads();

    // ---- per-class triangular whitening with channel-pair FFMA2.
    // zp accumulates (even-d partial, odd-d partial); per row fold into
    // P += zp*zp (packed) and cross += zp.lo*zp.hi (scalar).
    // maha = P.lo + P.hi + 2*cross.
    #pragma unroll 1
    for (int k = 0; k < NCLASS; k++) {
        const ull* Lk  = reinterpret_cast<const ull*>(sL + k * LFLTS);
        const ull* nwk = reinterpret_cast<const ull*>(sNW + k * NCH);
        ull  P0 = 0ULL, P1 = 0ULL, P2 = 0ULL, P3 = 0ULL;
        float c0 = 0.f, c1 = 0.f, c2 = 0.f, c3 = 0.f;
        int off = 0;
        #pragma unroll
        for (int c = 0; c < NCH; c++) {
            const int np = (c + 2) >> 1;      // channel-pairs in this padded row
            ull nv = nwk[c];                  // (-w, 0)
            ull z0 = nv, z1 = nv, z2 = nv, z3 = nv;
            #pragma unroll
            for (int j = 0; j < np; j++) {
                ull lw = Lk[off + j];         // one LDS.64 broadcast -> 4 FFMA2
                z0 = ffma2(xp[0][j], lw, z0);
                z1 = ffma2(xp[1][j], lw, z1);
                z2 = ffma2(xp[2][j], lw, z2);
                z3 = ffma2(xp[3][j], lw, z3);
            }
            off += np;
            float2 u0 = unpack2(z0), u1 = unpack2(z1);
            float2 u2 = unpack2(z2), u3 = unpack2(z3);
            P0 = ffma2(z0, z0, P0);  c0 = fmaf(u0.x, u0.y, c0);
            P1 = ffma2(z1, z1, P1);  c1 = fmaf(u1.x, u1.y, c1);
            P2 = ffma2(z2, z2, P2);  c2 = fmaf(u2.x, u2.y, c2);
            P3 = ffma2(z3, z3, P3);  c3 = fmaf(u3.x, u3.y, c3);
        }
        const float lc = sLogc[k];
        const int base = (tid * PPT) * 9 + k;
        float2 s0 = unpack2(P0), s1 = unpack2(P1);
        float2 s2 = unpack2(P2), s3 = unpack2(P3);
        sG[base     ] = fmaf(-0.5f, s0.x + s0.y, lc - c0);
        sG[base +  9] = fmaf(-0.5f, s1.x + s1.y, lc - c1);
        sG[base + 18] = fmaf(-0.5f, s2.x + s2.y, lc - c2);
        sG[base + 27] = fmaf(-0.5f, s3.x + s3.y, lc - c3);
    }

    // ---- epilogue: log-probs -> l2-normalized (with 1e-12 clamp) gauss weights
    #pragma unroll
    for (int q = 0; q < PPT; q++) {
        const int p = tid * PPT + q;
        float lp[NCLASS];
        #pragma unroll
        for (int k = 0; k < NCLASS; k++) lp[k] = sG[p * 9 + k];
        float m = lp[0];
        #pragma unroll
        for (int k = 1; k < NCLASS; k++) m = fmaxf(m, lp[k]);
        float pr[NCLASS];
        float s = 0.0f;
        #pragma unroll
        for (int k = 0; k < NCLASS; k++) {
            pr[k] = __expf(lp[k] - m);
            s = fmaf(pr[k], pr[k], s);     // s >= 1 always (max term is 1)
        }
        float em = __expf(m);
        float t = em * em * s;             // true sum(prob^2); underflow -> clamp path
        float sc = (t >= 1e-12f) ? rsqrtf(s) : (em * 1.0e6f);
        #pragma unroll
        for (int k = 0; k < NCLASS; k++) sG[p * 9 + k] = pr[k] * sc;
    }
    __syncthreads();

    // ---- store phase: one warp per pixel, fully coalesced 512B STG.128 bursts
    const int lane = tid & 31;
    const int wrp  = tid >> 5;
    const float4* x4 = reinterpret_cast<const float4*>(x);
    float4* o4 = reinterpret_cast<float4*>(out);
    for (int p = wrp; p < PPB; p += TPB / 32) {
        const size_t gp = (size_t)blockIdx.x * PPB + p;
        float4 xv = __ldg(&x4[gp * 8 + (lane & 7)]);        // one 128B line, L1/L2-hot
        float g0 = sG[p * 9 + (lane >> 3)];                 // classes 0..3
        float g1 = sG[p * 9 + 4 + (lane >> 3)];             // classes 4..7
        float4 r0, r1;
        r0.x = xv.x * g0; r0.y = xv.y * g0; r0.z = xv.z * g0; r0.w = xv.w * g0;
        r1.x = xv.x * g1; r1.y = xv.y * g1; r1.z = xv.z * g1; r1.w = xv.w * g1;
        __stcs(&o4[gp * 64 + lane],      r0);               // streaming: don't thrash L2
        __stcs(&o4[gp * 64 + 32 + lane], r1);
    }
}

extern "C" void kernel_launch(void* const* d_in, const int* in_sizes, int n_in,
                              void* d_out, int out_size) {
    const float* x     = (const float*)d_in[0];   // [8,256,256,32]
    const float* mean  = (const float*)d_in[1];   // [8,32]
    const float* scale = (const float*)d_in[2];   // [8,32,32]
    float* out = (float*)d_out;                   // [8,256,256,256]

    setup_kernel<<<1, 256>>>(mean, scale);
    main_kernel<<<NBLK, TPB>>>(x, out);
}